// round 1
// baseline (speedup 1.0000x reference)
#include <cuda_runtime.h>
#include <math.h>

#define BB 2
#define NN 4096
#define HEADS 8
#define DH 128
#define DIMM 1024
#define MM (BB*NN)          // 8192 rows
#define MAXMASK 2048
#define ATT_SCALE 0.03125f  // 1024^-0.5

// ---------------- scratch (static device allocations only) ----------------
__device__ float g_qT[(size_t)BB*HEADS*DH*NN];   // [bh][d][n] transposed
__device__ float g_kT[(size_t)BB*HEADS*DH*NN];   // [bh][d][n] transposed
__device__ float g_v [(size_t)BB*HEADS*NN*DH];   // [bh][n][d]
__device__ float g_att[(size_t)MM*DIMM];         // [b*n][dim]

// ---------------- SGEMM: C = A[M x 1024] * Bm[1024 x Ncols] ----------------
// 128x128 tile, BK=16, 256 threads, 8x8 microtile.
// MODE 0: A = x, Bm = W_qkv (Ncols=3072), scatter into g_qT/g_kT/g_v
// MODE 1: A = g_att, Bm = W_out (Ncols=1024), add bias, write out
template<int MODE>
__global__ __launch_bounds__(256) void sgemm_kernel(
    const float* __restrict__ A, const float* __restrict__ Bm,
    const float* __restrict__ bias, float* __restrict__ out, int Ncols)
{
    __shared__ float As[16][132];   // transposed A tile [k][m], padded
    __shared__ float Bs[16][128];   // B tile [k][n]

    const int tid = threadIdx.x;
    const int tx = tid & 15, ty = tid >> 4;
    const int row0 = blockIdx.y * 128;
    const int col0 = blockIdx.x * 128;
    const float* Ap = (MODE == 0) ? A : g_att;

    float acc[8][8];
#pragma unroll
    for (int i = 0; i < 8; i++)
#pragma unroll
        for (int j = 0; j < 8; j++) acc[i][j] = 0.f;

    for (int k0 = 0; k0 < 1024; k0 += 16) {
        // load A tile (128 rows x 16 k), store transposed
#pragma unroll
        for (int i = 0; i < 2; i++) {
            int p = tid + i * 256;              // 0..511
            int r = p >> 2;                     // 0..127
            int c4 = (p & 3) * 4;               // 0,4,8,12
            float4 v = *(const float4*)(Ap + (size_t)(row0 + r) * 1024 + k0 + c4);
            As[c4 + 0][r] = v.x; As[c4 + 1][r] = v.y;
            As[c4 + 2][r] = v.z; As[c4 + 3][r] = v.w;
        }
        // load B tile (16 k x 128 cols)
#pragma unroll
        for (int i = 0; i < 2; i++) {
            int p = tid + i * 256;
            int kk = p >> 5;                    // 0..15
            int c4 = (p & 31) * 4;              // 0..124
            *(float4*)(&Bs[kk][c4]) =
                *(const float4*)(Bm + (size_t)(k0 + kk) * Ncols + col0 + c4);
        }
        __syncthreads();

#pragma unroll
        for (int k = 0; k < 16; k++) {
            float a[8], b[8];
            *(float4*)(a)     = *(const float4*)(&As[k][ty * 8]);
            *(float4*)(a + 4) = *(const float4*)(&As[k][ty * 8 + 4]);
            *(float4*)(b)     = *(const float4*)(&Bs[k][tx * 8]);
            *(float4*)(b + 4) = *(const float4*)(&Bs[k][tx * 8 + 4]);
#pragma unroll
            for (int i = 0; i < 8; i++)
#pragma unroll
                for (int j = 0; j < 8; j++) acc[i][j] += a[i] * b[j];
        }
        __syncthreads();
    }

    if (MODE == 0) {
        // scatter to qT / kT / v
#pragma unroll
        for (int i = 0; i < 8; i++) {
            int gr = row0 + ty * 8 + i;
            int bb = gr >> 12;                  // /4096
            int n  = gr & 4095;
#pragma unroll
            for (int j = 0; j < 8; j++) {
                int gc = col0 + tx * 8 + j;
                int which  = gc >> 10;          // 0=q,1=k,2=v
                int within = gc & 1023;
                int h  = within >> 7;
                int dd = within & 127;
                int bh = bb * HEADS + h;
                float val = acc[i][j];
                if (which == 0)      g_qT[((size_t)bh * DH + dd) * NN + n] = val;
                else if (which == 1) g_kT[((size_t)bh * DH + dd) * NN + n] = val;
                else                 g_v [((size_t)bh * NN + n) * DH + dd] = val;
            }
        }
    } else {
#pragma unroll
        for (int i = 0; i < 8; i++) {
            int gr = row0 + ty * 8 + i;
#pragma unroll
            for (int j = 0; j < 8; j++) {
                int gc = col0 + tx * 8 + j;
                out[(size_t)gr * 1024 + gc] = acc[i][j] + bias[gc];
            }
        }
    }
}

// ---------------- Flash attention ----------------
// grid (64 i-tiles, 16 bh), 256 threads.
// S tile 64x64: thread (ty,tx) owns rows 4ty..+3, cols 4tx..+3.
// O tile 64x128: thread owns rows 4ty..+3, cols 8tx..+7.
#define QT_STRIDE 68
#define VS_STRIDE 132
#define SS_STRIDE 68
#define SMEM_ATTN ((128*QT_STRIDE*2 + 64*VS_STRIDE + 64*SS_STRIDE) * 4)

__global__ __launch_bounds__(256) void attn_kernel(const int* __restrict__ mask)
{
    extern __shared__ float sm[];
    float* Qt = sm;                          // [128][68]  k-major
    float* Kt = Qt + 128 * QT_STRIDE;        // [128][68]  k-major
    float* Vs = Kt + 128 * QT_STRIDE;        // [64][132]  row-major
    float* Ss = Vs + 64 * VS_STRIDE;         // [64][68]

    const int tid = threadIdx.x;
    const int tx = tid & 15, ty = tid >> 4;
    const int tx4 = tx * 4, ty4 = ty * 4, tx8 = tx * 8;
    const int it = blockIdx.x;
    const int bh = blockIdx.y;
    const int i0 = it * 64;

    const float* qT = g_qT + (size_t)bh * DH * NN;
    const float* kT = g_kT + (size_t)bh * DH * NN;
    const float* vP = g_v  + (size_t)bh * NN * DH;

    // load Q tile transposed into Qt[k][li]
#pragma unroll
    for (int i = 0; i < 8; i++) {
        int p = tid + i * 256;               // 0..2047
        int kk = p >> 4;                     // 0..127
        int c4 = (p & 15) * 4;               // 0..60
        *(float4*)(Qt + kk * QT_STRIDE + c4) =
            *(const float4*)(qT + (size_t)kk * NN + i0 + c4);
    }

    float O[4][8];
    float mrow[4], lrow[4];
#pragma unroll
    for (int r = 0; r < 4; r++) {
        mrow[r] = -INFINITY; lrow[r] = 0.f;
#pragma unroll
        for (int c = 0; c < 8; c++) O[r][c] = 0.f;
    }

    const bool irow_masked = (i0 < MAXMASK);

    for (int jt = 0; jt < 64; jt++) {
        const int j0 = jt * 64;
        __syncthreads();   // previous iter done with Kt/Vs/Ss
        // load K tile (transposed layout already in gmem)
#pragma unroll
        for (int i = 0; i < 8; i++) {
            int p = tid + i * 256;
            int kk = p >> 4;
            int c4 = (p & 15) * 4;
            *(float4*)(Kt + kk * QT_STRIDE + c4) =
                *(const float4*)(kT + (size_t)kk * NN + j0 + c4);
        }
        // load V tile row-major
#pragma unroll
        for (int i = 0; i < 8; i++) {
            int p = tid + i * 256;
            int r = p >> 5;                  // 0..63
            int c4 = (p & 31) * 4;           // 0..124
            *(float4*)(Vs + r * VS_STRIDE + c4) =
                *(const float4*)(vP + (size_t)(j0 + r) * DH + c4);
        }
        __syncthreads();

        // ---- S = Q K^T (4x4 microtile via outer products over k) ----
        float s[4][4];
#pragma unroll
        for (int r = 0; r < 4; r++)
#pragma unroll
            for (int c = 0; c < 4; c++) s[r][c] = 0.f;

#pragma unroll 8
        for (int k = 0; k < 128; k++) {
            float4 qv = *(const float4*)(Qt + k * QT_STRIDE + ty4);
            float4 kv = *(const float4*)(Kt + k * QT_STRIDE + tx4);
            float qa[4] = {qv.x, qv.y, qv.z, qv.w};
            float ka[4] = {kv.x, kv.y, kv.z, kv.w};
#pragma unroll
            for (int r = 0; r < 4; r++)
#pragma unroll
                for (int c = 0; c < 4; c++) s[r][c] += qa[r] * ka[c];
        }

        const bool msk = irow_masked && (j0 < MAXMASK);

        // ---- online softmax per owned row ----
#pragma unroll
        for (int rr = 0; rr < 4; rr++) {
            int li = ty4 + rr;
            int gi = i0 + li;
            float sv[4];
#pragma unroll
            for (int cc = 0; cc < 4; cc++) sv[cc] = s[rr][cc] * ATT_SCALE;
            if (msk) {
                const int4 mv = *(const int4*)(mask + (size_t)gi * MAXMASK + j0 + tx4);
                if (mv.x == 0) sv[0] = -INFINITY;
                if (mv.y == 0) sv[1] = -INFINITY;
                if (mv.z == 0) sv[2] = -INFINITY;
                if (mv.w == 0) sv[3] = -INFINITY;
            }
            float tmax = fmaxf(fmaxf(sv[0], sv[1]), fmaxf(sv[2], sv[3]));
#pragma unroll
            for (int w = 8; w >= 1; w >>= 1)
                tmax = fmaxf(tmax, __shfl_xor_sync(0xffffffffu, tmax, w));
            float nm = fmaxf(mrow[rr], tmax);
            float corr, p0, p1, p2, p3, rs;
            if (nm == -INFINITY) {           // fully masked so far: keep zeros
                corr = 1.f; p0 = p1 = p2 = p3 = 0.f; rs = 0.f;
            } else {
                corr = __expf(mrow[rr] - nm);
                p0 = __expf(sv[0] - nm); p1 = __expf(sv[1] - nm);
                p2 = __expf(sv[2] - nm); p3 = __expf(sv[3] - nm);
                rs = (p0 + p1) + (p2 + p3);
            }
#pragma unroll
            for (int w = 8; w >= 1; w >>= 1)
                rs += __shfl_xor_sync(0xffffffffu, rs, w);
            lrow[rr] = lrow[rr] * corr + rs;
            mrow[rr] = nm;
#pragma unroll
            for (int c = 0; c < 8; c++) O[rr][c] *= corr;
            *(float4*)(Ss + li * SS_STRIDE + tx4) = make_float4(p0, p1, p2, p3);
        }
        __syncthreads();

        // ---- O += P V ----
#pragma unroll 4
        for (int j4 = 0; j4 < 16; j4++) {
            float pr[4][4];
#pragma unroll
            for (int rr = 0; rr < 4; rr++) {
                float4 t = *(const float4*)(Ss + (ty4 + rr) * SS_STRIDE + j4 * 4);
                pr[rr][0] = t.x; pr[rr][1] = t.y; pr[rr][2] = t.z; pr[rr][3] = t.w;
            }
#pragma unroll
            for (int jj = 0; jj < 4; jj++) {
                float4 v0 = *(const float4*)(Vs + (j4 * 4 + jj) * VS_STRIDE + tx8);
                float4 v1 = *(const float4*)(Vs + (j4 * 4 + jj) * VS_STRIDE + tx8 + 4);
                float va[8] = {v0.x, v0.y, v0.z, v0.w, v1.x, v1.y, v1.z, v1.w};
#pragma unroll
                for (int rr = 0; rr < 4; rr++) {
                    float p = pr[rr][jj];
#pragma unroll
                    for (int c = 0; c < 8; c++) O[rr][c] += p * va[c];
                }
            }
        }
    }

    // ---- finalize: divide by l, store to g_att[b][n][h*128 + col] ----
    const int b = bh >> 3, h = bh & 7;
#pragma unroll
    for (int rr = 0; rr < 4; rr++) {
        float inv = 1.f / lrow[rr];
        int gi = i0 + ty4 + rr;
        size_t base = ((size_t)(b * NN + gi)) * DIMM + h * DH + tx8;
        float4 o0 = make_float4(O[rr][0] * inv, O[rr][1] * inv,
                                O[rr][2] * inv, O[rr][3] * inv);
        float4 o1 = make_float4(O[rr][4] * inv, O[rr][5] * inv,
                                O[rr][6] * inv, O[rr][7] * inv);
        *(float4*)(g_att + base)     = o0;
        *(float4*)(g_att + base + 4) = o1;
    }
}

// ---------------- launcher ----------------
extern "C" void kernel_launch(void* const* d_in, const int* in_sizes, int n_in,
                              void* d_out, int out_size)
{
    const float* x     = (const float*)d_in[0];   // [2,4096,1024]
    const float* W_qkv = (const float*)d_in[1];   // [1024,3072]
    const float* W_out = (const float*)d_in[2];   // [1024,1024]
    const float* b_out = (const float*)d_in[3];   // [1024]
    const int*   mask  = (const int*)  d_in[4];   // [1,1,2048,2048]
    float* out = (float*)d_out;                   // [2,4096,1024]

    cudaFuncSetAttribute(attn_kernel,
                         cudaFuncAttributeMaxDynamicSharedMemorySize, SMEM_ATTN);

    // 1) QKV projection + scatter (q,k transposed)
    sgemm_kernel<0><<<dim3(24, 64), 256>>>(x, W_qkv, nullptr, nullptr, 3072);

    // 2) flash attention
    attn_kernel<<<dim3(64, 16), 256, SMEM_ATTN>>>(mask);

    // 3) output projection + bias
    sgemm_kernel<1><<<dim3(8, 64), 256>>>(nullptr, W_out, b_out, out, 1024);
}

// round 3
// speedup vs baseline: 2.0128x; 2.0128x over previous
#include <cuda_runtime.h>
#include <math.h>
#include <stdint.h>

#define NN 4096
#define HEADS 8
#define DH 128
#define MAXMASK 2048
#define ATT_SCALE 0.03125f  // 1024^-0.5

// ---------------- scratch (static device allocations only) ----------------
__device__ float g_qT[(size_t)16*DH*NN];     // [bh][d][n]
__device__ float g_kT[(size_t)16*DH*NN];     // [bh][d][n]
__device__ float g_v [(size_t)16*NN*DH];     // [bh][n][d]
__device__ float g_att[(size_t)8192*1024];   // [b*n][dim]

// ---------------- tf32 mma.sync helpers ----------------
__device__ __forceinline__ uint32_t f2tf32(float x) {
    uint32_t r;
    asm("cvt.rna.tf32.f32 %0, %1;" : "=r"(r) : "f"(x));
    return r;
}
__device__ __forceinline__ void mma8(float* d, const uint32_t* a, const uint32_t* b) {
    asm volatile(
        "mma.sync.aligned.m16n8k8.row.col.f32.tf32.tf32.f32 "
        "{%0,%1,%2,%3}, {%4,%5,%6,%7}, {%8,%9}, {%0,%1,%2,%3};"
        : "+f"(d[0]), "+f"(d[1]), "+f"(d[2]), "+f"(d[3])
        : "r"(a[0]), "r"(a[1]), "r"(a[2]), "r"(a[3]), "r"(b[0]), "r"(b[1]));
}

// ================= tf32 tensor-core GEMM =================
// C[M x Ncols] = A[M x 1024] * Bm[1024 x Ncols]; CTA 128x128, BK=32.
// 8 warps in 2(m) x 4(n); warp tile 64x32 = 4 m-tiles x 4 n-tiles of m16n8k8.
// Fragment-order SMEM: A block [ks][mtile][32 slots][4 regs]; B [ks][ntile][32][2].
// MODE 0: A=x, Bm=W_qkv (3072) -> scatter q/k transposed + v
// MODE 1: A=g_att, Bm=W_out (1024) -> +bias -> out
template<int MODE>
__global__ __launch_bounds__(256) void mma_gemm(
    const float* __restrict__ A, const float* __restrict__ Bm,
    const float* __restrict__ bias, float* __restrict__ out, int Ncols)
{
    __shared__ uint32_t As[4*8*32*4];    // 16KB
    __shared__ uint32_t Bs[4*16*32*2];   // 8KB... (4*16*32*2*4 = 16KB)

    const int tid = threadIdx.x;
    const int lane = tid & 31, wid = tid >> 5;
    const int wm = wid >> 2, wn = wid & 3;
    const int m0 = blockIdx.y * 128, col0 = blockIdx.x * 128;
    const float* Ap = (MODE == 0) ? A : g_att;

    float acc[4][4][4];
#pragma unroll
    for (int mt = 0; mt < 4; mt++)
#pragma unroll
        for (int nt = 0; nt < 4; nt++)
#pragma unroll
            for (int r = 0; r < 4; r++) acc[mt][nt][r] = 0.f;

    for (int k0 = 0; k0 < 1024; k0 += 32) {
        __syncthreads();
        // A tile fill: 128 rows x 32 k
#pragma unroll
        for (int i = 0; i < 4; i++) {
            int p = tid + i * 256;
            int r = p >> 3, c4 = (p & 7) * 4;
            float4 v = *(const float4*)(Ap + (size_t)(m0 + r) * 1024 + k0 + c4);
            float vv[4] = {v.x, v.y, v.z, v.w};
#pragma unroll
            for (int e = 0; e < 4; e++) {
                int c = c4 + e;
                int ks = c >> 3, kk = c & 7;
                As[((ks * 8 + (r >> 4)) * 32 + (r & 7) * 4 + (kk & 3)) * 4
                   + ((r >> 3) & 1) + 2 * (kk >> 2)] = f2tf32(vv[e]);
            }
        }
        // B tile fill: 32 k x 128 n
#pragma unroll
        for (int i = 0; i < 4; i++) {
            int p = tid + i * 256;
            int kf = p >> 5, n4 = (p & 31) * 4;
            float4 v = *(const float4*)(Bm + (size_t)(k0 + kf) * Ncols + col0 + n4);
            float vv[4] = {v.x, v.y, v.z, v.w};
#pragma unroll
            for (int e = 0; e < 4; e++) {
                int n = n4 + e;
                Bs[((kf >> 3) * 16 + (n >> 3)) * 64 + ((n & 7) * 4 + (kf & 3)) * 2
                   + ((kf & 7) >> 2)] = f2tf32(vv[e]);
            }
        }
        __syncthreads();

#pragma unroll
        for (int ks = 0; ks < 4; ks++) {
            uint32_t a[4][4], b[4][2];
#pragma unroll
            for (int mt = 0; mt < 4; mt++)
                *(uint4*)a[mt] = *(const uint4*)&As[((ks * 8 + wm * 4 + mt) * 32 + lane) * 4];
#pragma unroll
            for (int nt = 0; nt < 4; nt++)
                *(uint2*)b[nt] = *(const uint2*)&Bs[(ks * 16 + wn * 4 + nt) * 64 + lane * 2];
#pragma unroll
            for (int mt = 0; mt < 4; mt++)
#pragma unroll
                for (int nt = 0; nt < 4; nt++)
                    mma8(acc[mt][nt], a[mt], b[nt]);
        }
    }

    const int g = lane >> 2, l2 = (lane & 3) * 2;
    if (MODE == 0) {
        const int which = col0 >> 10;          // 0=q 1=k 2=v
        const int h = (col0 & 1023) >> 7;
#pragma unroll
        for (int mt = 0; mt < 4; mt++) {
#pragma unroll
            for (int nt = 0; nt < 4; nt++) {
                int col = col0 + wn * 32 + nt * 8 + l2;
                int dd = col & 127;
#pragma unroll
                for (int hf = 0; hf < 2; hf++) {
                    int gr = m0 + wm * 64 + mt * 16 + g + hf * 8;
                    int b = gr >> 12, n = gr & 4095;
                    int bh = b * HEADS + h;
                    float v0 = acc[mt][nt][hf * 2], v1 = acc[mt][nt][hf * 2 + 1];
                    if (which == 2) {
                        *(float2*)(g_v + ((size_t)bh * NN + n) * DH + dd) =
                            make_float2(v0, v1);
                    } else {
                        float* dst = (which == 0 ? g_qT : g_kT)
                                     + ((size_t)bh * DH + dd) * NN + n;
                        dst[0] = v0; dst[NN] = v1;
                    }
                }
            }
        }
    } else {
#pragma unroll
        for (int mt = 0; mt < 4; mt++)
#pragma unroll
            for (int nt = 0; nt < 4; nt++) {
                int col = col0 + wn * 32 + nt * 8 + l2;
                float2 bb = *(const float2*)(bias + col);
#pragma unroll
                for (int hf = 0; hf < 2; hf++) {
                    int gr = m0 + wm * 64 + mt * 16 + g + hf * 8;
                    *(float2*)(out + (size_t)gr * 1024 + col) =
                        make_float2(acc[mt][nt][hf * 2] + bb.x,
                                    acc[mt][nt][hf * 2 + 1] + bb.y);
                }
            }
    }
}

// ================= Flash attention (mma.sync tf32) =================
// CTA: 128 q-rows x (j-tiles of 64) x d=128. 8 warps; warp w owns rows 16w..16w+15.
// S: per warp 1 m-tile x 8 n-tiles, k=128 (16 ksteps).
// PV: per warp 1 m-tile x 16 n-tiles (d), k=64 (8 ksteps).
#define KV_BLK 33   // padded slot count per (kstep,ntile) block (8B slots)
#define QF_WORDS   (16*8*32*4)       // 16384
#define KF_WORDS   (16*8*KV_BLK*2)   // 8448
#define VF_WORDS   (8*16*KV_BLK*2)   // 8448
#define PF_WORDS   (8*8*32*4)        // 8192
#define ATT_SMEM   ((QF_WORDS + KF_WORDS + VF_WORDS + PF_WORDS) * 4)  // 165888 B

__global__ __launch_bounds__(256) void attn_kernel(const int* __restrict__ mask)
{
    extern __shared__ uint32_t sm4[];
    uint32_t* Qf = sm4;
    uint32_t* Kf = Qf + QF_WORDS;
    uint32_t* Vf = Kf + KF_WORDS;
    uint32_t* Pf = Vf + VF_WORDS;

    const int tid = threadIdx.x;
    const int lane = tid & 31, wid = tid >> 5;
    const int g = lane >> 2, l2 = (lane & 3) * 2;
    const int i0 = blockIdx.x * 128;
    const int bh = blockIdx.y;

    const float* qT = g_qT + (size_t)bh * DH * NN;
    const float* kT = g_kT + (size_t)bh * DH * NN;
    const float* vP = g_v  + (size_t)bh * NN * DH;

    // ---- Q fill (once per CTA), pre-scaled by ATT_SCALE ----
#pragma unroll
    for (int i = 0; i < 16; i++) {
        int p = tid + i * 256;
        int d = p >> 5, i4 = (p & 31) * 4;
        float4 v = *(const float4*)(qT + (size_t)d * NN + i0 + i4);
        float vv[4] = {v.x, v.y, v.z, v.w};
        int ks = d >> 3, kk = d & 7;
#pragma unroll
        for (int e = 0; e < 4; e++) {
            int ii = i4 + e;
            Qf[((ks * 8 + (ii >> 4)) * 32 + ((ii & 7) * 4 + (kk & 3))) * 4
               + (((ii >> 3) & 1)) + 2 * (kk >> 2)] = f2tf32(vv[e] * ATT_SCALE);
        }
    }

    float oacc[16][4];
#pragma unroll
    for (int nt = 0; nt < 16; nt++)
#pragma unroll
        for (int r = 0; r < 4; r++) oacc[nt][r] = 0.f;
    float mrow[2] = {-INFINITY, -INFINITY};
    float lrow[2] = {0.f, 0.f};

    for (int jt = 0; jt < 64; jt++) {
        const int j0 = jt * 64;
        __syncthreads();
        // ---- K fill: 128 d x 64 j, scalar loads (coalesced), 2-way max STS conflicts
#pragma unroll
        for (int i = 0; i < 32; i++) {
            int p = tid + i * 256;
            int d = p >> 6, jj = p & 63;
            float val = kT[(size_t)d * NN + j0 + jj];
            Kf[((d >> 3) * 8 + (jj >> 3)) * (KV_BLK * 2)
               + ((jj & 7) * 4 + (d & 3)) * 2 + ((d & 7) >> 2)] = f2tf32(val);
        }
        // ---- V fill: 64 j x 128 d
#pragma unroll
        for (int i = 0; i < 32; i++) {
            int p = tid + i * 256;
            int d = p & 127, jj = p >> 7;
            float val = vP[(size_t)(j0 + jj) * DH + d];
            Vf[((jj >> 3) * 16 + (d >> 3)) * (KV_BLK * 2)
               + ((d & 7) * 4 + (jj & 3)) * 2 + ((jj & 7) >> 2)] = f2tf32(val);
        }
        __syncthreads();

        // ---- S = (Q*scale) K^T ----
        float sacc[8][4];
#pragma unroll
        for (int nt = 0; nt < 8; nt++)
#pragma unroll
            for (int r = 0; r < 4; r++) sacc[nt][r] = 0.f;
#pragma unroll
        for (int ks = 0; ks < 16; ks++) {
            uint32_t a[4];
            *(uint4*)a = *(const uint4*)&Qf[((ks * 8 + wid) * 32 + lane) * 4];
#pragma unroll
            for (int nt = 0; nt < 8; nt++) {
                uint32_t b[2];
                *(uint2*)b = *(const uint2*)&Kf[(ks * 8 + nt) * (KV_BLK * 2) + lane * 2];
                mma8(sacc[nt], a, b);
            }
        }

        // ---- mask ----
        if (i0 < MAXMASK && j0 < MAXMASK) {
#pragma unroll
            for (int hf = 0; hf < 2; hf++) {
                int gi = i0 + wid * 16 + g + hf * 8;
                const int* mp = mask + (size_t)gi * MAXMASK + j0;
#pragma unroll
                for (int nt = 0; nt < 8; nt++) {
                    int2 mv = *(const int2*)(mp + nt * 8 + l2);
                    if (mv.x == 0) sacc[nt][hf * 2]     = -INFINITY;
                    if (mv.y == 0) sacc[nt][hf * 2 + 1] = -INFINITY;
                }
            }
        }

        // ---- online softmax (rows fully within warp; quad shuffles) ----
#pragma unroll
        for (int hf = 0; hf < 2; hf++) {
            float tmax = -INFINITY;
#pragma unroll
            for (int nt = 0; nt < 8; nt++)
                tmax = fmaxf(tmax, fmaxf(sacc[nt][hf * 2], sacc[nt][hf * 2 + 1]));
            tmax = fmaxf(tmax, __shfl_xor_sync(0xffffffffu, tmax, 1));
            tmax = fmaxf(tmax, __shfl_xor_sync(0xffffffffu, tmax, 2));
            float nm = fmaxf(mrow[hf], tmax);
            float corr, rs = 0.f;
            if (nm == -INFINITY) {
                corr = 1.f;
#pragma unroll
                for (int nt = 0; nt < 8; nt++) {
                    sacc[nt][hf * 2] = 0.f; sacc[nt][hf * 2 + 1] = 0.f;
                }
            } else {
                corr = __expf(mrow[hf] - nm);
#pragma unroll
                for (int nt = 0; nt < 8; nt++) {
                    float p0 = __expf(sacc[nt][hf * 2] - nm);
                    float p1 = __expf(sacc[nt][hf * 2 + 1] - nm);
                    sacc[nt][hf * 2] = p0; sacc[nt][hf * 2 + 1] = p1;
                    rs += p0 + p1;
                }
            }
            rs += __shfl_xor_sync(0xffffffffu, rs, 1);
            rs += __shfl_xor_sync(0xffffffffu, rs, 2);
            lrow[hf] = lrow[hf] * corr + rs;
            mrow[hf] = nm;
#pragma unroll
            for (int nt = 0; nt < 16; nt++) {
                oacc[nt][hf * 2]     *= corr;
                oacc[nt][hf * 2 + 1] *= corr;
            }
        }

        // ---- P -> A-fragment layout in SMEM (warp-private block) ----
#pragma unroll
        for (int nt = 0; nt < 8; nt++) {
#pragma unroll
            for (int idx = 0; idx < 4; idx++) {
                int e = idx & 1, hf = idx >> 1;
                int kk = l2 + e;
                Pf[((nt * 8 + wid) * 32 + g * 4 + (kk & 3)) * 4 + hf + 2 * (kk >> 2)]
                    = f2tf32(sacc[nt][hf * 2 + e]);
            }
        }
        __syncwarp();

        // ---- O += P V ----
#pragma unroll
        for (int ks = 0; ks < 8; ks++) {
            uint32_t a[4];
            *(uint4*)a = *(const uint4*)&Pf[((ks * 8 + wid) * 32 + lane) * 4];
#pragma unroll
            for (int nt = 0; nt < 16; nt++) {
                uint32_t b[2];
                *(uint2*)b = *(const uint2*)&Vf[(ks * 16 + nt) * (KV_BLK * 2) + lane * 2];
                mma8(oacc[nt], a, b);
            }
        }
    }

    // ---- finalize ----
    const int b = bh >> 3, h = bh & 7;
#pragma unroll
    for (int hf = 0; hf < 2; hf++) {
        float inv = 1.f / lrow[hf];
        int r = i0 + wid * 16 + g + hf * 8;
        size_t base = ((size_t)(b * NN + r)) * 1024 + h * DH;
#pragma unroll
        for (int nt = 0; nt < 16; nt++) {
            *(float2*)(g_att + base + nt * 8 + l2) =
                make_float2(oacc[nt][hf * 2] * inv, oacc[nt][hf * 2 + 1] * inv);
        }
    }
}

// ---------------- launcher ----------------
extern "C" void kernel_launch(void* const* d_in, const int* in_sizes, int n_in,
                              void* d_out, int out_size)
{
    const float* x     = (const float*)d_in[0];   // [2,4096,1024]
    const float* W_qkv = (const float*)d_in[1];   // [1024,3072]
    const float* W_out = (const float*)d_in[2];   // [1024,1024]
    const float* b_out = (const float*)d_in[3];   // [1024]
    const int*   mask  = (const int*)  d_in[4];   // [1,1,2048,2048]
    float* out = (float*)d_out;                   // [2,4096,1024]

    cudaFuncSetAttribute(attn_kernel,
                         cudaFuncAttributeMaxDynamicSharedMemorySize, ATT_SMEM);

    // 1) QKV projection (tf32 mma) + scatter
    mma_gemm<0><<<dim3(24, 64), 256>>>(x, W_qkv, nullptr, nullptr, 3072);

    // 2) flash attention (tf32 mma)
    attn_kernel<<<dim3(32, 16), 256, ATT_SMEM>>>(mask);

    // 3) output projection (tf32 mma) + bias
    mma_gemm<1><<<dim3(8, 64), 256>>>(nullptr, W_out, b_out, out, 1024);
}

// round 4
// speedup vs baseline: 4.8881x; 2.4286x over previous
#include <cuda_runtime.h>
#include <math.h>
#include <stdint.h>

#define NN 4096
#define HEADS 8
#define DH 128
#define MAXMASK 2048
#define ATT_SCALE 0.03125f  // 1024^-0.5

// ---------------- scratch ----------------
__device__ float g_q  [(size_t)16*NN*DH];    // [bh][n][d]
__device__ float g_k  [(size_t)16*NN*DH];    // [bh][n][d]
__device__ float g_vT [(size_t)16*DH*NN];    // [bh][d][n]
__device__ float g_att[(size_t)8192*1024];   // [b*n][dim]
__device__ float g_wqkvT[(size_t)3072*1024]; // W_qkv^T
__device__ float g_woutT[(size_t)1024*1024]; // W_out^T

// ---------------- helpers ----------------
__device__ __forceinline__ uint32_t smem_u32(const void* p) {
    uint32_t a;
    asm("{ .reg .u64 t; cvta.to.shared.u64 t, %1; cvt.u32.u64 %0, t; }"
        : "=r"(a) : "l"(p));
    return a;
}
__device__ __forceinline__ void cp16(uint32_t sdst, const void* gsrc) {
    asm volatile("cp.async.cg.shared.global [%0], [%1], 16;"
                 :: "r"(sdst), "l"(gsrc) : "memory");
}
#define CP_COMMIT() asm volatile("cp.async.commit_group;" ::: "memory")
#define CP_WAIT(n)  asm volatile("cp.async.wait_group %0;" :: "n"(n) : "memory")

__device__ __forceinline__ void ldsm4(uint32_t* r, uint32_t saddr) {
    asm volatile("ldmatrix.sync.aligned.m8n8.x4.shared.b16 {%0,%1,%2,%3}, [%4];"
        : "=r"(r[0]), "=r"(r[1]), "=r"(r[2]), "=r"(r[3]) : "r"(saddr));
}
__device__ __forceinline__ void mma8(float* d, const uint32_t* a, const uint32_t* b) {
    asm volatile(
        "mma.sync.aligned.m16n8k8.row.col.f32.tf32.tf32.f32 "
        "{%0,%1,%2,%3}, {%4,%5,%6,%7}, {%8,%9}, {%0,%1,%2,%3};"
        : "+f"(d[0]), "+f"(d[1]), "+f"(d[2]), "+f"(d[3])
        : "r"(a[0]), "r"(a[1]), "r"(a[2]), "r"(a[3]), "r"(b[0]), "r"(b[1]));
}
// swizzled smem byte offset: row of ROWB bytes, 16B slots, slot ^= (row&7)
__device__ __forceinline__ uint32_t swz(int row, int slot, int rowb) {
    return (uint32_t)(row * rowb + ((slot ^ (row & 7)) << 4));
}

// ---------------- weight transpose: in[R][C] -> out[C][R] ----------------
__global__ void transpose_k(const float* __restrict__ in, float* __restrict__ outp,
                            int R, int C)
{
    __shared__ float t[32][33];
    int bx = blockIdx.x * 32, by = blockIdx.y * 32;
    int tx = threadIdx.x, ty = threadIdx.y;  // 32 x 8
#pragma unroll
    for (int i = 0; i < 32; i += 8)
        t[ty + i][tx] = in[(size_t)(by + ty + i) * C + bx + tx];
    __syncthreads();
#pragma unroll
    for (int i = 0; i < 32; i += 8)
        outp[(size_t)(bx + ty + i) * R + by + tx] = t[tx][ty + i];
}

// ================= GEMM: C[M x Ncols] = A[M x 1024] * Bt[Ncols x 1024]^T =======
// CTA 128x128, BK=32, cp.async double-buffered, ldmatrix, warps 2m x 4n (64x32).
#define GEMM_SMEM 65536
template<int MODE>
__global__ __launch_bounds__(256) void mma_gemm(
    const float* __restrict__ A, const float* __restrict__ Bt,
    const float* __restrict__ bias, float* __restrict__ out)
{
    extern __shared__ char sm[];
    const uint32_t sb = smem_u32(sm);
    const int tid = threadIdx.x, lane = tid & 31, wid = tid >> 5;
    const int wm = wid >> 2, wn = wid & 3;
    const int g = lane >> 2, l4 = lane & 3;
    const int m0 = blockIdx.y * 128, col0 = blockIdx.x * 128;

    const int arow_l = (lane & 7) + ((lane >> 3) & 1) * 8;
    const int asel = (lane >> 4) & 1;
    const int brow_l = (lane & 7) + ((lane >> 4) & 1) * 8;
    const int bsel = (lane >> 3) & 1;

    float acc[4][4][4];
#pragma unroll
    for (int mt = 0; mt < 4; mt++)
#pragma unroll
        for (int nt = 0; nt < 4; nt++)
#pragma unroll
            for (int r = 0; r < 4; r++) acc[mt][nt][r] = 0.f;

    auto fill = [&](int buf, int k0) {
#pragma unroll
        for (int i = 0; i < 4; i++) {
            int p = tid + i * 256;
            int r = p >> 3, s = p & 7;
            cp16(sb + buf * 16384 + swz(r, s, 128),
                 A + (size_t)(m0 + r) * 1024 + k0 + s * 4);
        }
#pragma unroll
        for (int i = 0; i < 4; i++) {
            int p = tid + i * 256;
            int r = p >> 3, s = p & 7;
            cp16(sb + 32768 + buf * 16384 + swz(r, s, 128),
                 Bt + (size_t)(col0 + r) * 1024 + k0 + s * 4);
        }
    };

    fill(0, 0);
    CP_COMMIT();

    for (int kb = 0; kb < 32; kb++) {
        if (kb < 31) { fill((kb + 1) & 1, (kb + 1) * 32); CP_COMMIT(); CP_WAIT(1); }
        else CP_WAIT(0);
        __syncthreads();
        const uint32_t ab = sb + (kb & 1) * 16384;
        const uint32_t bb = sb + 32768 + (kb & 1) * 16384;
#pragma unroll
        for (int ks = 0; ks < 4; ks++) {
            uint32_t a[4][4], b[2][4];
#pragma unroll
            for (int mt = 0; mt < 4; mt++) {
                int row = wm * 64 + mt * 16 + arow_l;
                ldsm4(a[mt], ab + swz(row, 2 * ks + asel, 128));
            }
#pragma unroll
            for (int pr = 0; pr < 2; pr++) {
                int row = wn * 32 + pr * 16 + brow_l;
                ldsm4(b[pr], bb + swz(row, 2 * ks + bsel, 128));
            }
#pragma unroll
            for (int mt = 0; mt < 4; mt++)
#pragma unroll
                for (int nt = 0; nt < 4; nt++)
                    mma8(acc[mt][nt], a[mt], &b[nt >> 1][(nt & 1) * 2]);
        }
        __syncthreads();
    }

    if (MODE == 0) {
        const int which = col0 >> 10;          // 0=q 1=k 2=v
        const int h = (col0 & 1023) >> 7;
#pragma unroll
        for (int mt = 0; mt < 4; mt++)
#pragma unroll
            for (int nt = 0; nt < 4; nt++) {
                int col = col0 + wn * 32 + nt * 8 + 2 * l4;
                int dd = col & 127;
#pragma unroll
                for (int hf = 0; hf < 2; hf++) {
                    int gr = m0 + wm * 64 + mt * 16 + g + 8 * hf;
                    int bb2 = gr >> 12, n = gr & 4095;
                    int bh = bb2 * HEADS + h;
                    float c0 = acc[mt][nt][hf * 2], c1 = acc[mt][nt][hf * 2 + 1];
                    if (which == 0)
                        *(float2*)(g_q + ((size_t)bh * NN + n) * DH + dd) = make_float2(c0, c1);
                    else if (which == 1)
                        *(float2*)(g_k + ((size_t)bh * NN + n) * DH + dd) = make_float2(c0, c1);
                    else {
                        float* dst = g_vT + ((size_t)bh * DH + dd) * NN + n;
                        dst[0] = c0; dst[NN] = c1;
                    }
                }
            }
    } else {
#pragma unroll
        for (int mt = 0; mt < 4; mt++)
#pragma unroll
            for (int nt = 0; nt < 4; nt++) {
                int col = col0 + wn * 32 + nt * 8 + 2 * l4;
                float2 bv = *(const float2*)(bias + col);
#pragma unroll
                for (int hf = 0; hf < 2; hf++) {
                    int gr = m0 + wm * 64 + mt * 16 + g + 8 * hf;
                    *(float2*)(out + (size_t)gr * 1024 + col) =
                        make_float2(acc[mt][nt][hf * 2] + bv.x,
                                    acc[mt][nt][hf * 2 + 1] + bv.y);
                }
            }
    }
}

// ================= Flash attention (ldmatrix + cp.async) =================
// i-tile 128, j-tile 64. 8 warps: S role (wm 0..3, wj 0..1) warp 32 rows x 32 j;
// PV role (wm, wd) warp 32 rows x 64 d. Q resident; K double-buffered; V single.
#define QS_OFF   0          // 128 x 512B = 64KB
#define K_OFF(b) (65536 + (b) * 32768)   // 64 x 512B each
#define VS_OFF   131072     // 128 x 256B = 32KB   (V^T: rows=d, cols=j)
#define PS_OFF   163840     // 128 x 256B = 32KB   (P: rows=i, cols=j)
#define REDM_OFF 196608     // float[128][2]
#define REDS_OFF 197632     // float[128][2]
#define ATT_SMEM 198656

__global__ __launch_bounds__(256) void attn_kernel(const int* __restrict__ mask)
{
    extern __shared__ char sm[];
    const uint32_t sb = smem_u32(sm);
    float (*redm)[2] = (float(*)[2])(sm + REDM_OFF);
    float (*reds)[2] = (float(*)[2])(sm + REDS_OFF);

    const int tid = threadIdx.x, lane = tid & 31, wid = tid >> 5;
    const int wm = wid & 3, wg = wid >> 2;   // wg = wj (S) = wd (PV)
    const int g = lane >> 2, l4 = lane & 3;
    const int i0 = blockIdx.x * 128;
    const int bh = blockIdx.y;

    const float* qP  = g_q  + (size_t)bh * NN * DH;
    const float* kP  = g_k  + (size_t)bh * NN * DH;
    const float* vTP = g_vT + (size_t)bh * DH * NN;

    const int arow_l = (lane & 7) + ((lane >> 3) & 1) * 8;
    const int asel = (lane >> 4) & 1;
    const int brow_l = (lane & 7) + ((lane >> 4) & 1) * 8;
    const int bsel = (lane >> 3) & 1;

    // Q fill (group 1)
#pragma unroll
    for (int i = 0; i < 16; i++) {
        int p = tid + i * 256;
        int r = p >> 5, s = p & 31;
        cp16(sb + QS_OFF + swz(r, s, 512), qP + (size_t)(i0 + r) * DH + s * 4);
    }
    CP_COMMIT();
    // K(0) fill (group 2)
#pragma unroll
    for (int i = 0; i < 8; i++) {
        int p = tid + i * 256;
        int r = p >> 5, s = p & 31;
        cp16(sb + K_OFF(0) + swz(r, s, 512), kP + (size_t)r * DH + s * 4);
    }
    CP_COMMIT();

    float oacc[2][8][4];
#pragma unroll
    for (int mt = 0; mt < 2; mt++)
#pragma unroll
        for (int nt = 0; nt < 8; nt++)
#pragma unroll
            for (int r = 0; r < 4; r++) oacc[mt][nt][r] = 0.f;
    float mreg[2][2] = {{-1e30f, -1e30f}, {-1e30f, -1e30f}};
    float lreg[2][2] = {{0.f, 0.f}, {0.f, 0.f}};

    for (int jt = 0; jt < 64; jt++) {
        const int j0 = jt * 64;
        __syncthreads();   // prev PV done with V / P buffers

        // V(jt) fill (V^T rows = d)
#pragma unroll
        for (int i = 0; i < 8; i++) {
            int p = tid + i * 256;
            int r = p >> 4, s = p & 15;
            cp16(sb + VS_OFF + swz(r, s, 256), vTP + (size_t)r * NN + j0 + s * 4);
        }
        CP_COMMIT();
        CP_WAIT(1);        // K(jt) (and Q) complete; V may be pending
        __syncthreads();

        // ---- S = Q K^T ----
        float sacc[2][4][4];
#pragma unroll
        for (int mt = 0; mt < 2; mt++)
#pragma unroll
            for (int nt = 0; nt < 4; nt++)
#pragma unroll
                for (int r = 0; r < 4; r++) sacc[mt][nt][r] = 0.f;

        const uint32_t kb = sb + K_OFF(jt & 1);
#pragma unroll
        for (int ks = 0; ks < 16; ks++) {
            uint32_t a[2][4], b[2][4];
#pragma unroll
            for (int mt = 0; mt < 2; mt++) {
                int row = wm * 32 + mt * 16 + arow_l;
                ldsm4(a[mt], sb + QS_OFF + swz(row, 2 * ks + asel, 512));
            }
#pragma unroll
            for (int pr = 0; pr < 2; pr++) {
                int row = wg * 32 + pr * 16 + brow_l;
                ldsm4(b[pr], kb + swz(row, 2 * ks + bsel, 512));
            }
#pragma unroll
            for (int mt = 0; mt < 2; mt++)
#pragma unroll
                for (int nt = 0; nt < 4; nt++)
                    mma8(sacc[mt][nt], a[mt], &b[nt >> 1][(nt & 1) * 2]);
        }

        // prefetch K(jt+1)
        if (jt < 63) {
            const float* kn = kP + (size_t)(j0 + 64) * DH;
#pragma unroll
            for (int i = 0; i < 8; i++) {
                int p = tid + i * 256;
                int r = p >> 5, s = p & 31;
                cp16(sb + K_OFF((jt + 1) & 1) + swz(r, s, 512),
                     kn + (size_t)r * DH + s * 4);
            }
            CP_COMMIT();
        }

        // ---- scale + mask ----
#pragma unroll
        for (int mt = 0; mt < 2; mt++)
#pragma unroll
            for (int nt = 0; nt < 4; nt++)
#pragma unroll
                for (int r = 0; r < 4; r++) sacc[mt][nt][r] *= ATT_SCALE;
        if (i0 < MAXMASK && j0 < MAXMASK) {
#pragma unroll
            for (int mt = 0; mt < 2; mt++)
#pragma unroll
                for (int hf = 0; hf < 2; hf++) {
                    int gi = i0 + wm * 32 + mt * 16 + g + 8 * hf;
                    const int* mp = mask + (size_t)gi * MAXMASK + j0 + wg * 32;
#pragma unroll
                    for (int nt = 0; nt < 4; nt++) {
                        int2 mv = *(const int2*)(mp + nt * 8 + 2 * l4);
                        if (mv.x == 0) sacc[mt][nt][hf * 2]     = -INFINITY;
                        if (mv.y == 0) sacc[mt][nt][hf * 2 + 1] = -INFINITY;
                    }
                }
        }

        // ---- softmax stage 1: per-row partial max ----
#pragma unroll
        for (int mt = 0; mt < 2; mt++)
#pragma unroll
            for (int hf = 0; hf < 2; hf++) {
                float pm = -INFINITY;
#pragma unroll
                for (int nt = 0; nt < 4; nt++)
                    pm = fmaxf(pm, fmaxf(sacc[mt][nt][hf * 2], sacc[mt][nt][hf * 2 + 1]));
                pm = fmaxf(pm, __shfl_xor_sync(0xffffffffu, pm, 1));
                pm = fmaxf(pm, __shfl_xor_sync(0xffffffffu, pm, 2));
                if (l4 == 0) redm[wm * 32 + mt * 16 + g + 8 * hf][wg] = pm;
            }
        __syncthreads();

        // ---- softmax stage 2: combine, exp, partial sums, P store ----
        float corr[2][2];
#pragma unroll
        for (int mt = 0; mt < 2; mt++)
#pragma unroll
            for (int hf = 0; hf < 2; hf++) {
                int lr = wm * 32 + mt * 16 + g + 8 * hf;
                float nm = fmaxf(fmaxf(redm[lr][0], redm[lr][1]), mreg[mt][hf]);
                float mc = fmaxf(nm, -1e30f);
                corr[mt][hf] = __expf(mreg[mt][hf] - mc);
                mreg[mt][hf] = mc;
                float rs = 0.f;
#pragma unroll
                for (int nt = 0; nt < 4; nt++) {
                    float p0 = __expf(sacc[mt][nt][hf * 2]     - mc);
                    float p1 = __expf(sacc[mt][nt][hf * 2 + 1] - mc);
                    sacc[mt][nt][hf * 2] = p0; sacc[mt][nt][hf * 2 + 1] = p1;
                    rs += p0 + p1;
                    // P store
                    int cslot = wg * 8 + nt * 2 + (l4 >> 1);
                    *(float2*)(sm + PS_OFF + lr * 256
                               + ((cslot ^ (lr & 7)) << 4) + (l4 & 1) * 8) =
                        make_float2(p0, p1);
                }
                rs += __shfl_xor_sync(0xffffffffu, rs, 1);
                rs += __shfl_xor_sync(0xffffffffu, rs, 2);
                if (l4 == 0) reds[lr][wg] = rs;
            }
        if (jt < 63) CP_WAIT(1); else CP_WAIT(0);   // V complete
        __syncthreads();

        // ---- l update + O rescale ----
#pragma unroll
        for (int mt = 0; mt < 2; mt++)
#pragma unroll
            for (int hf = 0; hf < 2; hf++) {
                int lr = wm * 32 + mt * 16 + g + 8 * hf;
                lreg[mt][hf] = lreg[mt][hf] * corr[mt][hf] + reds[lr][0] + reds[lr][1];
#pragma unroll
                for (int nt = 0; nt < 8; nt++) {
                    oacc[mt][nt][hf * 2]     *= corr[mt][hf];
                    oacc[mt][nt][hf * 2 + 1] *= corr[mt][hf];
                }
            }

        // ---- O += P V ----
#pragma unroll
        for (int ks = 0; ks < 8; ks++) {
            uint32_t a[2][4], b[4][4];
#pragma unroll
            for (int mt = 0; mt < 2; mt++) {
                int row = wm * 32 + mt * 16 + arow_l;
                ldsm4(a[mt], sb + PS_OFF + swz(row, 2 * ks + asel, 256));
            }
#pragma unroll
            for (int pr = 0; pr < 4; pr++) {
                int row = wg * 64 + pr * 16 + brow_l;
                ldsm4(b[pr], sb + VS_OFF + swz(row, 2 * ks + bsel, 256));
            }
#pragma unroll
            for (int mt = 0; mt < 2; mt++)
#pragma unroll
                for (int nt = 0; nt < 8; nt++)
                    mma8(oacc[mt][nt], a[mt], &b[nt >> 1][(nt & 1) * 2]);
        }
    }

    // ---- finalize ----
    const int b = bh >> 3, h = bh & 7;
#pragma unroll
    for (int mt = 0; mt < 2; mt++)
#pragma unroll
        for (int hf = 0; hf < 2; hf++) {
            float inv = 1.f / lreg[mt][hf];
            int gi = i0 + wm * 32 + mt * 16 + g + 8 * hf;
            size_t base = ((size_t)(b * NN + gi)) * 1024 + h * DH + wg * 64;
#pragma unroll
            for (int nt = 0; nt < 8; nt++)
                *(float2*)(g_att + base + nt * 8 + 2 * l4) =
                    make_float2(oacc[mt][nt][hf * 2] * inv,
                                oacc[mt][nt][hf * 2 + 1] * inv);
        }
}

// ---------------- launcher ----------------
extern "C" void kernel_launch(void* const* d_in, const int* in_sizes, int n_in,
                              void* d_out, int out_size)
{
    const float* x     = (const float*)d_in[0];
    const float* W_qkv = (const float*)d_in[1];
    const float* W_out = (const float*)d_in[2];
    const float* b_out = (const float*)d_in[3];
    const int*   mask  = (const int*)  d_in[4];
    float* out = (float*)d_out;

    cudaFuncSetAttribute(attn_kernel,
                         cudaFuncAttributeMaxDynamicSharedMemorySize, ATT_SMEM);
    cudaFuncSetAttribute(mma_gemm<0>,
                         cudaFuncAttributeMaxDynamicSharedMemorySize, GEMM_SMEM);
    cudaFuncSetAttribute(mma_gemm<1>,
                         cudaFuncAttributeMaxDynamicSharedMemorySize, GEMM_SMEM);

    float* wqkvT; cudaGetSymbolAddress((void**)&wqkvT, g_wqkvT);
    float* woutT; cudaGetSymbolAddress((void**)&woutT, g_woutT);
    float* att;   cudaGetSymbolAddress((void**)&att, g_att);

    transpose_k<<<dim3(96, 32), dim3(32, 8)>>>(W_qkv, wqkvT, 1024, 3072);
    transpose_k<<<dim3(32, 32), dim3(32, 8)>>>(W_out, woutT, 1024, 1024);

    mma_gemm<0><<<dim3(24, 64), 256, GEMM_SMEM>>>(x, wqkvT, nullptr, nullptr);
    attn_kernel<<<dim3(32, 16), 256, ATT_SMEM>>>(mask);
    mma_gemm<1><<<dim3(8, 64), 256, GEMM_SMEM>>>(att, woutT, b_out, out);
}